// round 16
// baseline (speedup 1.0000x reference)
#include <cuda_runtime.h>
#include <math.h>
#include <stdint.h>

#define NN 50000
#define EE 800000
#define HH 64
#define FF 64
#define CC 10
#define KK 4
#define LL 3
#define NB_BATCH 256
#define SPAD 68
#define WSPAD 72

// ---------------- device scratch ----------------
__device__ float g_Z[NN * HH];
__device__ float g_h0[(size_t)NN * KK * HH];
__device__ float g_h1[(size_t)NN * KK * HH];
__device__ float g_AB[(size_t)KK * NN * 128];
__device__ float g_ewc[(size_t)EE * KK];
__device__ float g_Wsp[32 * 8192];            // 32 pre-split matrices: [hi 4096 | lo 4096]
__device__ int   g_deg[NN];
__device__ int   g_off[NN + 1];
__device__ int   g_fill[NN];
__device__ int   g_csr_src[EE + 4];
__device__ int   g_csr_eid[EE];
__device__ float g_poolZ[NB_BATCH * HH];
__device__ float g_poolS[KK * NB_BATCH * HH];
__device__ int   g_cnt[NB_BATCH];

__device__ __forceinline__ void red_add_f2(float* p, float a, float b) {
    asm volatile("red.global.add.v2.f32 [%0], {%1,%2};"
                 :: "l"(p), "f"(a), "f"(b) : "memory");
}
__device__ __forceinline__ float sigmoidf_(float v) { return 1.0f / (1.0f + expf(-v)); }

__device__ __forceinline__ uint32_t tf32_rna(float a) {
    uint32_t h; asm("cvt.rna.tf32.f32 %0, %1;" : "=r"(h) : "f"(a)); return h;
}

// pure-copy load of a pre-split matrix into smem hi/lo planes
__device__ __forceinline__ void loadWpre(int mat, float* Wh, float* Wl, int tid) {
    const float4* src = (const float4*)(g_Wsp + (size_t)mat * 8192);
    #pragma unroll
    for (int it = 0; it < 8; it++) {
        int i = it * 256 + tid;               // 0..2047
        float4 w = src[i];
        int plane = i >> 10, idx = i & 1023;
        int k = idx >> 4, j = (idx & 15) * 4;
        float* dstp = plane ? Wl : Wh;
        *((float4*)&dstp[k * WSPAD + j]) = w;
    }
}

#define MMA_TF32(c, A0, A1, A2, A3, B0, B1) \
    asm("mma.sync.aligned.m16n8k8.row.col.f32.tf32.tf32.f32 " \
        "{%0,%1,%2,%3}, {%4,%5,%6,%7}, {%8,%9}, {%0,%1,%2,%3};" \
        : "+f"((c)[0]), "+f"((c)[1]), "+f"((c)[2]), "+f"((c)[3]) \
        : "r"(A0), "r"(A1), "r"(A2), "r"(A3), "r"(B0), "r"(B1))

__device__ __forceinline__ void gemm_frag(const float* As, const float* Wh,
                                          const float* Wl, float c[4][4],
                                          int lane, int warp) {
    int mband = (warp & 3) * 16, nhalf = (warp >> 2) * 32;
    int lr = lane >> 2, lc = lane & 3;
    #pragma unroll
    for (int nt = 0; nt < 4; nt++)
        #pragma unroll
        for (int q = 0; q < 4; q++) c[nt][q] = 0.f;
    #pragma unroll
    for (int ks = 0; ks < 8; ks++) {
        int k0 = ks * 8;
        float a0 = As[(mband + lr) * SPAD + k0 + lc];
        float a1 = As[(mband + 8 + lr) * SPAD + k0 + lc];
        float a2 = As[(mband + lr) * SPAD + k0 + 4 + lc];
        float a3 = As[(mband + 8 + lr) * SPAD + k0 + 4 + lc];
        uint32_t ah0 = tf32_rna(a0), ah1 = tf32_rna(a1);
        uint32_t ah2 = tf32_rna(a2), ah3 = tf32_rna(a3);
        uint32_t al0 = tf32_rna(a0 - __uint_as_float(ah0));
        uint32_t al1 = tf32_rna(a1 - __uint_as_float(ah1));
        uint32_t al2 = tf32_rna(a2 - __uint_as_float(ah2));
        uint32_t al3 = tf32_rna(a3 - __uint_as_float(ah3));
        #pragma unroll
        for (int nt = 0; nt < 4; nt++) {
            int n = nhalf + nt * 8 + lr;
            uint32_t bh0 = __float_as_uint(Wh[(k0 + lc) * WSPAD + n]);
            uint32_t bl0 = __float_as_uint(Wl[(k0 + lc) * WSPAD + n]);
            uint32_t bh1 = __float_as_uint(Wh[(k0 + 4 + lc) * WSPAD + n]);
            uint32_t bl1 = __float_as_uint(Wl[(k0 + 4 + lc) * WSPAD + n]);
            MMA_TF32(c[nt], ah0, ah1, ah2, ah3, bh0, bh1);
            MMA_TF32(c[nt], al0, al1, al2, al3, bh0, bh1);
            MMA_TF32(c[nt], ah0, ah1, ah2, ah3, bl0, bl1);
        }
    }
}

__device__ __forceinline__ void stage_frag(const float c[4][4], float* Cs,
                                           int lane, int warp) {
    int mband = (warp & 3) * 16, nhalf = (warp >> 2) * 32;
    int lr = lane >> 2, lc = lane & 3;
    #pragma unroll
    for (int nt = 0; nt < 4; nt++) {
        int col = nhalf + nt * 8 + lc * 2;
        *((float2*)&Cs[(mband + lr) * SPAD + col])     = make_float2(c[nt][0], c[nt][1]);
        *((float2*)&Cs[(mband + 8 + lr) * SPAD + col]) = make_float2(c[nt][2], c[nt][3]);
    }
}

__device__ __forceinline__ void read_acc(const float* Cs, float acc[4][4],
                                         int tx, int ty) {
    #pragma unroll
    for (int i = 0; i < 4; i++) {
        float4 v = *((const float4*)&Cs[(ty * 4 + i) * SPAD + tx * 4]);
        acc[i][0] = v.x; acc[i][1] = v.y; acc[i][2] = v.z; acc[i][3] = v.w;
    }
}

__device__ __forceinline__ void frag_relu_to_As(const float c[4][4], const float* bsh,
                                                float* As, int lane, int warp) {
    int mband = (warp & 3) * 16, nhalf = (warp >> 2) * 32;
    int lr = lane >> 2, lc = lane & 3;
    #pragma unroll
    for (int nt = 0; nt < 4; nt++) {
        int col = nhalf + nt * 8 + lc * 2;
        float b0 = bsh[col], b1 = bsh[col + 1];
        *((float2*)&As[(mband + lr) * SPAD + col]) =
            make_float2(fmaxf(c[nt][0] + b0, 0.f), fmaxf(c[nt][1] + b1, 0.f));
        *((float2*)&As[(mband + 8 + lr) * SPAD + col]) =
            make_float2(fmaxf(c[nt][2] + b0, 0.f), fmaxf(c[nt][3] + b1, 0.f));
    }
}

// ---------------- weight pre-split prep ----------------
// mats: 0-2 ceW1[l], 3-5 ceW2[l], 6-8 clW1[l], 9-11 clW2[l], 12-15 nmW1[k],
//       16-23 emW1[k half], 24-27 fmW1[k], 28-31 fmW2[k]
__global__ __launch_bounds__(256) void prep_kernel(
    const float* __restrict__ ceW1, const float* __restrict__ ceW2,
    const float* __restrict__ clW1, const float* __restrict__ clW2,
    const float* __restrict__ nmW1, const float* __restrict__ emW1,
    const float* __restrict__ fmW1, const float* __restrict__ fmW2)
{
    int m = blockIdx.x;
    const float* src;
    if      (m < 3)  src = ceW1 + (size_t)m * 4096;
    else if (m < 6)  src = ceW2 + (size_t)(m - 3) * 4096;
    else if (m < 9)  src = clW1 + (size_t)(m - 6) * 4096;
    else if (m < 12) src = clW2 + (size_t)(m - 9) * 4096;
    else if (m < 16) src = nmW1 + (size_t)(m - 12) * 4096;
    else if (m < 24) src = emW1 + (size_t)(m - 16) * 4096;
    else if (m < 28) src = fmW1 + (size_t)(m - 24) * 4096;
    else             src = fmW2 + (size_t)(m - 28) * 4096;
    float* dh = g_Wsp + (size_t)m * 8192;
    float* dl = dh + 4096;
    int tid = threadIdx.x;
    #pragma unroll
    for (int it = 0; it < 4; it++) {
        int i = it * 256 + tid;              // float4 index 0..1023
        float4 w = ((const float4*)src)[i];
        float4 h, l;
        h.x = __uint_as_float(tf32_rna(w.x)); l.x = __uint_as_float(tf32_rna(w.x - h.x));
        h.y = __uint_as_float(tf32_rna(w.y)); l.y = __uint_as_float(tf32_rna(w.y - h.y));
        h.z = __uint_as_float(tf32_rna(w.z)); l.z = __uint_as_float(tf32_rna(w.z - h.z));
        h.w = __uint_as_float(tf32_rna(w.w)); l.w = __uint_as_float(tf32_rna(w.w - h.w));
        ((float4*)dh)[i] = h;
        ((float4*)dl)[i] = l;
    }
}

// ---------------- init ----------------
__global__ __launch_bounds__(256) void init_kernel() {
    int i = blockIdx.x * 256 + threadIdx.x;
    if (i < NN) { g_deg[i] = 0; g_fill[i] = 0; }
    if (i < NB_BATCH) g_cnt[i] = 0;
    if (i < NB_BATCH * HH) g_poolZ[i] = 0.f;
    if (i < KK * NB_BATCH * HH) g_poolS[i] = 0.f;
    if (i < 4) g_csr_src[EE + i] = 0;
}

__global__ __launch_bounds__(256) void histcnt_kernel(const int* __restrict__ dst,
                                                      const int* __restrict__ batch) {
    int e = blockIdx.x * 256 + threadIdx.x;
    if (e < EE) atomicAdd(&g_deg[dst[e]], 1);
    if (e < NN) atomicAdd(&g_cnt[batch[e]], 1);
}

__global__ __launch_bounds__(1024) void scan_kernel() {
    __shared__ int wsum[32];
    __shared__ int carry_s;
    int tid = threadIdx.x, lane = tid & 31, wid = tid >> 5;
    if (tid == 0) carry_s = 0;
    __syncthreads();
    for (int base = 0; base < NN; base += 1024) {
        int v = (base + tid < NN) ? g_deg[base + tid] : 0;
        int inc = v;
        #pragma unroll
        for (int off = 1; off < 32; off <<= 1) {
            int t = __shfl_up_sync(0xffffffffu, inc, off);
            if (lane >= off) inc += t;
        }
        if (lane == 31) wsum[wid] = inc;
        __syncthreads();
        if (wid == 0) {
            int s = wsum[lane];
            #pragma unroll
            for (int off = 1; off < 32; off <<= 1) {
                int t = __shfl_up_sync(0xffffffffu, s, off);
                if (lane >= off) s += t;
            }
            wsum[lane] = s;
        }
        __syncthreads();
        int wpre = wid ? wsum[wid - 1] : 0;
        int excl = carry_s + wpre + inc - v;
        if (base + tid < NN) g_off[base + tid] = excl;
        __syncthreads();
        if (tid == 0) carry_s += wsum[31];
        __syncthreads();
    }
    if (threadIdx.x == 0) g_off[NN] = carry_s;
}

__global__ __launch_bounds__(256) void fill_kernel(const int* __restrict__ src,
                                                   const int* __restrict__ dst) {
    int e = blockIdx.x * 256 + threadIdx.x;
    if (e < EE) {
        int d = dst[e];
        int pos = g_off[d] + atomicAdd(&g_fill[d], 1);
        g_csr_src[pos] = src[e];
        g_csr_eid[pos] = e;
    }
}

// ---------------- encoder GIN layer ----------------
__global__ __launch_bounds__(256) void ginenc_kernel(
    const float* __restrict__ hin, float* __restrict__ hout,
    const float* __restrict__ eps_ptr, int lidx, int w1mat, int w2mat,
    const float* __restrict__ b1, const float* __restrict__ b2,
    float* __restrict__ pool, const int* __restrict__ batch)
{
    __shared__ __align__(16) float As[64 * SPAD];
    __shared__ __align__(16) float Wh[64 * WSPAD];
    __shared__ __align__(16) float Wl[64 * WSPAD];
    __shared__ float bsh[64], bsh2[64];
    int tid = threadIdx.x;
    int r0 = blockIdx.x * 64;
    float epsv = 1.0f + eps_ptr[lidx];
    int part = tid & 15, grp = tid >> 4;
    int lane = tid & 31, warp = tid >> 5;

    #pragma unroll
    for (int rr = 0; rr < 4; rr++) {
        int row = rr * 16 + grp;
        int gr = r0 + row;
        float4 a = make_float4(0.f, 0.f, 0.f, 0.f);
        if (gr < NN) {
            float4 h = ((const float4*)(hin + (size_t)gr * HH))[part];
            a.x = epsv * h.x; a.y = epsv * h.y; a.z = epsv * h.z; a.w = epsv * h.w;
            int beg = g_off[gr], end = g_off[gr + 1];
            int p = beg;
            int sA = g_csr_src[p], sB = g_csr_src[p + 1];
            for (; p + 1 < end; p += 2) {
                int s0 = sA, s1 = sB;
                sA = g_csr_src[p + 2]; sB = g_csr_src[p + 3];
                float4 v0 = ((const float4*)(hin + (size_t)s0 * HH))[part];
                float4 v1 = ((const float4*)(hin + (size_t)s1 * HH))[part];
                a.x += v0.x + v1.x; a.y += v0.y + v1.y;
                a.z += v0.z + v1.z; a.w += v0.w + v1.w;
            }
            if (p < end) {
                float4 v0 = ((const float4*)(hin + (size_t)sA * HH))[part];
                a.x += v0.x; a.y += v0.y; a.z += v0.z; a.w += v0.w;
            }
        }
        *((float4*)&As[row * SPAD + part * 4]) = a;
    }

    loadWpre(w1mat, Wh, Wl, tid);
    if (tid < 64) { bsh[tid] = b1[tid]; bsh2[tid] = b2[tid]; }
    __syncthreads();

    float c[4][4];
    gemm_frag(As, Wh, Wl, c, lane, warp);
    __syncthreads();
    frag_relu_to_As(c, bsh, As, lane, warp);
    loadWpre(w2mat, Wh, Wl, tid);
    __syncthreads();
    gemm_frag(As, Wh, Wl, c, lane, warp);

    {
        int mband = (warp & 3) * 16, nhalf = (warp >> 2) * 32;
        int lr = lane >> 2, lc = lane & 3;
        int ga = r0 + mband + lr, gb = r0 + mband + 8 + lr;
        int bA = 0, bB = 0;
        if (pool) {
            if (ga < NN) bA = batch[ga];
            if (gb < NN) bB = batch[gb];
        }
        #pragma unroll
        for (int nt = 0; nt < 4; nt++) {
            int col = nhalf + nt * 8 + lc * 2;
            float b0 = bsh2[col], b1v = bsh2[col + 1];
            if (ga < NN) {
                float ox = fmaxf(c[nt][0] + b0, 0.f), oy = fmaxf(c[nt][1] + b1v, 0.f);
                *((float2*)(hout + (size_t)ga * HH + col)) = make_float2(ox, oy);
                if (pool) red_add_f2(pool + (size_t)bA * HH + col, ox, oy);
            }
            if (gb < NN) {
                float ox = fmaxf(c[nt][2] + b0, 0.f), oy = fmaxf(c[nt][3] + b1v, 0.f);
                *((float2*)(hout + (size_t)gb * HH + col)) = make_float2(ox, oy);
                if (pool) red_add_f2(pool + (size_t)bB * HH + col, ox, oy);
            }
        }
    }
}

// ---------------- classifier GIN layer ----------------
__global__ __launch_bounds__(256) void gincl_kernel(
    const float* __restrict__ hin, float* __restrict__ hout,
    const float* __restrict__ eps_ptr, int lidx, int w1mat, int w2mat,
    const float* __restrict__ b1, const float* __restrict__ b2,
    float* __restrict__ pool, const int* __restrict__ batch)
{
    __shared__ __align__(16) float As[64 * SPAD];
    __shared__ __align__(16) float Wh[64 * WSPAD];
    __shared__ __align__(16) float Wl[64 * WSPAD];
    __shared__ float bsh[64], bsh2[64];
    int tid = threadIdx.x;
    int n0 = blockIdx.x * 16;
    float epsv = 1.0f + eps_ptr[lidx];
    int part = tid & 15, grp = tid >> 4;
    int lane = tid & 31, warp = tid >> 5;

    {
        int gr = n0 + grp;
        const float4* hbase = (const float4*)(hin + (size_t)gr * KK * HH);
        float4 a[4];
        #pragma unroll
        for (int k = 0; k < 4; k++) {
            float4 h = hbase[k * 16 + part];
            a[k].x = epsv * h.x; a[k].y = epsv * h.y;
            a[k].z = epsv * h.z; a[k].w = epsv * h.w;
        }
        int beg = g_off[gr], end = g_off[gr + 1];
        int p = beg;
        int sA = g_csr_src[p], sB = g_csr_src[p + 1];
        for (; p + 1 < end; p += 2) {
            int s0 = sA, s1 = sB;
            sA = g_csr_src[p + 2]; sB = g_csr_src[p + 3];
            float4 w0 = *((const float4*)(g_ewc + (size_t)p * 4));
            float4 w1 = *((const float4*)(g_ewc + (size_t)(p + 1) * 4));
            const float4* vb0 = (const float4*)(hin + (size_t)s0 * KK * HH);
            const float4* vb1 = (const float4*)(hin + (size_t)s1 * KK * HH);
            float4 v0 = vb0[0 * 16 + part];
            float4 v1 = vb0[1 * 16 + part];
            float4 v2 = vb0[2 * 16 + part];
            float4 v3 = vb0[3 * 16 + part];
            float4 u0 = vb1[0 * 16 + part];
            float4 u1 = vb1[1 * 16 + part];
            float4 u2 = vb1[2 * 16 + part];
            float4 u3 = vb1[3 * 16 + part];
            a[0].x = fmaf(w0.x, v0.x, a[0].x); a[0].y = fmaf(w0.x, v0.y, a[0].y);
            a[0].z = fmaf(w0.x, v0.z, a[0].z); a[0].w = fmaf(w0.x, v0.w, a[0].w);
            a[1].x = fmaf(w0.y, v1.x, a[1].x); a[1].y = fmaf(w0.y, v1.y, a[1].y);
            a[1].z = fmaf(w0.y, v1.z, a[1].z); a[1].w = fmaf(w0.y, v1.w, a[1].w);
            a[2].x = fmaf(w0.z, v2.x, a[2].x); a[2].y = fmaf(w0.z, v2.y, a[2].y);
            a[2].z = fmaf(w0.z, v2.z, a[2].z); a[2].w = fmaf(w0.z, v2.w, a[2].w);
            a[3].x = fmaf(w0.w, v3.x, a[3].x); a[3].y = fmaf(w0.w, v3.y, a[3].y);
            a[3].z = fmaf(w0.w, v3.z, a[3].z); a[3].w = fmaf(w0.w, v3.w, a[3].w);
            a[0].x = fmaf(w1.x, u0.x, a[0].x); a[0].y = fmaf(w1.x, u0.y, a[0].y);
            a[0].z = fmaf(w1.x, u0.z, a[0].z); a[0].w = fmaf(w1.x, u0.w, a[0].w);
            a[1].x = fmaf(w1.y, u1.x, a[1].x); a[1].y = fmaf(w1.y, u1.y, a[1].y);
            a[1].z = fmaf(w1.y, u1.z, a[1].z); a[1].w = fmaf(w1.y, u1.w, a[1].w);
            a[2].x = fmaf(w1.z, u2.x, a[2].x); a[2].y = fmaf(w1.z, u2.y, a[2].y);
            a[2].z = fmaf(w1.z, u2.z, a[2].z); a[2].w = fmaf(w1.z, u2.w, a[2].w);
            a[3].x = fmaf(w1.w, u3.x, a[3].x); a[3].y = fmaf(w1.w, u3.y, a[3].y);
            a[3].z = fmaf(w1.w, u3.z, a[3].z); a[3].w = fmaf(w1.w, u3.w, a[3].w);
        }
        if (p < end) {
            float4 w0 = *((const float4*)(g_ewc + (size_t)p * 4));
            const float4* vb = (const float4*)(hin + (size_t)sA * KK * HH);
            float4 v0 = vb[0 * 16 + part];
            float4 v1 = vb[1 * 16 + part];
            float4 v2 = vb[2 * 16 + part];
            float4 v3 = vb[3 * 16 + part];
            a[0].x = fmaf(w0.x, v0.x, a[0].x); a[0].y = fmaf(w0.x, v0.y, a[0].y);
            a[0].z = fmaf(w0.x, v0.z, a[0].z); a[0].w = fmaf(w0.x, v0.w, a[0].w);
            a[1].x = fmaf(w0.y, v1.x, a[1].x); a[1].y = fmaf(w0.y, v1.y, a[1].y);
            a[1].z = fmaf(w0.y, v1.z, a[1].z); a[1].w = fmaf(w0.y, v1.w, a[1].w);
            a[2].x = fmaf(w0.z, v2.x, a[2].x); a[2].y = fmaf(w0.z, v2.y, a[2].y);
            a[2].z = fmaf(w0.z, v2.z, a[2].z); a[2].w = fmaf(w0.z, v2.w, a[2].w);
            a[3].x = fmaf(w0.w, v3.x, a[3].x); a[3].y = fmaf(w0.w, v3.y, a[3].y);
            a[3].z = fmaf(w0.w, v3.z, a[3].z); a[3].w = fmaf(w0.w, v3.w, a[3].w);
        }
        #pragma unroll
        for (int k = 0; k < 4; k++)
            *((float4*)&As[(grp * 4 + k) * SPAD + part * 4]) = a[k];
    }

    loadWpre(w1mat, Wh, Wl, tid);
    if (tid < 64) { bsh[tid] = b1[tid]; bsh2[tid] = b2[tid]; }
    __syncthreads();

    float c[4][4];
    gemm_frag(As, Wh, Wl, c, lane, warp);
    __syncthreads();
    frag_relu_to_As(c, bsh, As, lane, warp);
    loadWpre(w2mat, Wh, Wl, tid);
    __syncthreads();
    gemm_frag(As, Wh, Wl, c, lane, warp);

    {
        int mband = (warp & 3) * 16, nhalf = (warp >> 2) * 32;
        int lr = lane >> 2, lc = lane & 3;
        int ra = mband + lr, rb = mband + 8 + lr;
        int gna = n0 + (ra >> 2), kea = ra & 3;
        int gnb = n0 + (rb >> 2), keb = rb & 3;
        int bA = 0, bB = 0;
        if (pool) { bA = batch[gna]; bB = batch[gnb]; }
        float* ha = hout + ((size_t)gna * KK + kea) * HH;
        float* hb = hout + ((size_t)gnb * KK + keb) * HH;
        #pragma unroll
        for (int nt = 0; nt < 4; nt++) {
            int col = nhalf + nt * 8 + lc * 2;
            float b0 = bsh2[col], b1v = bsh2[col + 1];
            float ox = fmaxf(c[nt][0] + b0, 0.f), oy = fmaxf(c[nt][1] + b1v, 0.f);
            *((float2*)(ha + col)) = make_float2(ox, oy);
            if (pool) red_add_f2(pool + ((size_t)kea * NB_BATCH + bA) * HH + col, ox, oy);
            float px = fmaxf(c[nt][2] + b0, 0.f), py = fmaxf(c[nt][3] + b1v, 0.f);
            *((float2*)(hb + col)) = make_float2(px, py);
            if (pool) red_add_f2(pool + ((size_t)keb * NB_BATCH + bB) * HH + col, px, py);
        }
    }
}

// ---------------- fused mask kernel ----------------
__global__ __launch_bounds__(256) void mask_kernel(
    const float* __restrict__ Z, const float* __restrict__ x,
    const float* __restrict__ nmb1, const float* __restrict__ nmW2,
    const float* __restrict__ nmb2,
    const float* __restrict__ fmb1, const float* __restrict__ fmb2,
    float* __restrict__ out_nm, float* __restrict__ out_fm)
{
    __shared__ __align__(16) float As[64 * SPAD];
    __shared__ __align__(16) float Wh[64 * WSPAD];
    __shared__ __align__(16) float Wl[64 * WSPAD];
    __shared__ float bsh[64], bsh2[64], w2s[64], nmv[64];
    int tid = threadIdx.x, r0 = blockIdx.x * 64;
    int k = blockIdx.y;
    int lane = tid & 31, warp = tid >> 5;
    int mband = (warp & 3) * 16, nhalf = (warp >> 2) * 32;
    int lr = lane >> 2, lc = lane & 3;
    float* ABk = g_AB + (size_t)k * NN * 128;

    {
        int row = tid >> 2, p0 = (tid & 3) * 4, gr = r0 + row;
        #pragma unroll
        for (int q = 0; q < 4; q++) {
            float4 v = make_float4(0.f, 0.f, 0.f, 0.f);
            if (gr < NN) v = ((const float4*)(Z + (size_t)gr * HH))[p0 + q];
            *((float4*)&As[row * SPAD + (p0 + q) * 4]) = v;
        }
    }
    int tx = tid & 15, ty = tid >> 4;
    float c[4][4], acc[4][4];
    int ga = r0 + mband + lr, gb = r0 + mband + 8 + lr;

    // ---- node mask (staged, cross-warp reduce) ----
    loadWpre(12 + k, Wh, Wl, tid);
    if (tid < 64) { bsh[tid] = nmb1[k * 64 + tid]; w2s[tid] = nmW2[k * 64 + tid]; }
    __syncthreads();
    gemm_frag(As, Wh, Wl, c, lane, warp);
    __syncthreads();
    stage_frag(c, Wh, lane, warp);
    __syncthreads();
    read_acc(Wh, acc, tx, ty);
    float b2v = nmb2[k];
    #pragma unroll
    for (int i = 0; i < 4; i++) {
        float p = 0.f;
        #pragma unroll
        for (int j = 0; j < 4; j++)
            p += fmaxf(acc[i][j] + bsh[tx*4+j], 0.f) * w2s[tx*4+j];
        #pragma unroll
        for (int off = 8; off > 0; off >>= 1)
            p += __shfl_down_sync(0xffffffffu, p, off, 16);
        if (tx == 0) {
            float sg = sigmoidf_(p + b2v);
            nmv[ty * 4 + i] = sg;
            int gr = r0 + ty * 4 + i;
            if (gr < NN) out_nm[(size_t)gr * KK + k] = sg;
        }
    }
    __syncthreads();

    // ---- AB precompute (fragment-direct) ----
    #pragma unroll
    for (int half = 0; half < 2; half++) {
        loadWpre(16 + 2 * k + half, Wh, Wl, tid);
        __syncthreads();
        gemm_frag(As, Wh, Wl, c, lane, warp);
        #pragma unroll
        for (int nt = 0; nt < 4; nt++) {
            int col = half * 64 + nhalf + nt * 8 + lc * 2;
            if (ga < NN)
                *((float2*)(ABk + (size_t)ga * 128 + col)) = make_float2(c[nt][0], c[nt][1]);
            if (gb < NN)
                *((float2*)(ABk + (size_t)gb * 128 + col)) = make_float2(c[nt][2], c[nt][3]);
        }
        __syncthreads();
    }

    // ---- feature mask + masked_x ----
    loadWpre(24 + k, Wh, Wl, tid);
    if (tid < 64) { bsh[tid] = fmb1[k * 64 + tid]; bsh2[tid] = fmb2[k * 64 + tid]; }
    __syncthreads();
    gemm_frag(As, Wh, Wl, c, lane, warp);
    __syncthreads();
    frag_relu_to_As(c, bsh, As, lane, warp);
    loadWpre(28 + k, Wh, Wl, tid);
    __syncthreads();
    gemm_frag(As, Wh, Wl, c, lane, warp);

    {
        float nmu_a = (ga < NN) ? nmv[mband + lr] : 0.f;
        float nmu_b = (gb < NN) ? nmv[mband + 8 + lr] : 0.f;
        #pragma unroll
        for (int nt = 0; nt < 4; nt++) {
            int col = nhalf + nt * 8 + lc * 2;
            float b0 = bsh2[col], b1v = bsh2[col + 1];
            if (ga < NN) {
                float2 xr = *((const float2*)(x + (size_t)ga * FF + col));
                float sx = sigmoidf_(c[nt][0] + b0), sy = sigmoidf_(c[nt][1] + b1v);
                *((float2*)(out_fm + ((size_t)ga * KK + k) * FF + col)) = make_float2(sx, sy);
                *((float2*)(g_h0 + ((size_t)ga * KK + k) * HH + col)) =
                    make_float2(xr.x * nmu_a * sx, xr.y * nmu_a * sy);
            }
            if (gb < NN) {
                float2 xr = *((const float2*)(x + (size_t)gb * FF + col));
                float sx = sigmoidf_(c[nt][2] + b0), sy = sigmoidf_(c[nt][3] + b1v);
                *((float2*)(out_fm + ((size_t)gb * KK + k) * FF + col)) = make_float2(sx, sy);
                *((float2*)(g_h0 + ((size_t)gb * KK + k) * HH + col)) =
                    make_float2(xr.x * nmu_b * sx, xr.y * nmu_b * sy);
            }
        }
    }
}

// ---------------- edge mask: CSR-row-tiled, ALL K experts in one pass ----------------
__global__ __launch_bounds__(256) void edge_mask_kernel(
    const float* __restrict__ emb1, const float* __restrict__ emW2,
    const float* __restrict__ emb2, float* __restrict__ out_em)
{
    __shared__ __align__(16) float b1s[4][64];
    __shared__ __align__(16) float w2s[4][64];
    int tid = threadIdx.x;
    {
        int kk = tid >> 6, j = tid & 63;
        b1s[kk][j] = emb1[kk * 64 + j];
        w2s[kk][j] = emW2[kk * 64 + j];
    }
    __syncthreads();
    int lane = tid & 15, grp = tid >> 4;
    int gr = blockIdx.x * 16 + grp;

    float4 bb[4], w[4];
    float b2v[4];
    #pragma unroll
    for (int k = 0; k < 4; k++) {
        const float* ABk = g_AB + (size_t)k * NN * 128;
        float4 b = *((const float4*)(ABk + (size_t)gr * 128 + 64) + lane);
        float4 bi = ((const float4*)b1s[k])[lane];
        bb[k] = make_float4(b.x + bi.x, b.y + bi.y, b.z + bi.z, b.w + bi.w);
        w[k] = ((const float4*)w2s[k])[lane];
        b2v[k] = emb2[k];
    }

    int beg = g_off[gr], end = g_off[gr + 1];
    for (int p = beg; p < end; p++) {
        int s = g_csr_src[p];
        float pp[4];
        #pragma unroll
        for (int k = 0; k < 4; k++) {
            const float* ABk = g_AB + (size_t)k * NN * 128;
            float4 a = *((const float4*)(ABk + (size_t)s * 128) + lane);
            pp[k] = fmaxf(a.x + bb[k].x, 0.f) * w[k].x
                  + fmaxf(a.y + bb[k].y, 0.f) * w[k].y
                  + fmaxf(a.z + bb[k].z, 0.f) * w[k].z
                  + fmaxf(a.w + bb[k].w, 0.f) * w[k].w;
        }
        #pragma unroll
        for (int off = 8; off > 0; off >>= 1) {
            pp[0] += __shfl_down_sync(0xffffffffu, pp[0], off, 16);
            pp[1] += __shfl_down_sync(0xffffffffu, pp[1], off, 16);
            pp[2] += __shfl_down_sync(0xffffffffu, pp[2], off, 16);
            pp[3] += __shfl_down_sync(0xffffffffu, pp[3], off, 16);
        }
        if (lane == 0) {
            float4 sg;
            sg.x = sigmoidf_(pp[0] + b2v[0]);
            sg.y = sigmoidf_(pp[1] + b2v[1]);
            sg.z = sigmoidf_(pp[2] + b2v[2]);
            sg.w = sigmoidf_(pp[3] + b2v[3]);
            *((float4*)(g_ewc + (size_t)p * 4)) = sg;
            *((float4*)(out_em + (size_t)g_csr_eid[p] * 4)) = sg;
        }
    }
}

// ---------------- finalize ----------------
__global__ __launch_bounds__(64) void finalize_kernel(
    const float* __restrict__ clfW, const float* __restrict__ clfb,
    float* __restrict__ out_logits, float* __restrict__ out_hstab,
    float* __restrict__ out_horig)
{
    int b = blockIdx.x, t = threadIdx.x;
    __shared__ float hs[64];
    float inv = 1.0f / fmaxf((float)g_cnt[b], 1.0f);
    out_horig[b * HH + t] = g_poolZ[b * HH + t] * inv;
    for (int k = 0; k < KK; k++) {
        float v = g_poolS[((size_t)k * NB_BATCH + b) * HH + t] * inv;
        out_hstab[((size_t)b * KK + k) * HH + t] = v;
        hs[t] = v;
        __syncthreads();
        if (t < CC) {
            float sacc = clfb[k * CC + t];
            #pragma unroll 8
            for (int h2 = 0; h2 < HH; h2++)
                sacc += hs[h2] * clfW[((size_t)k * HH + h2) * CC + t];
            out_logits[((size_t)b * KK + k) * CC + t] = sacc;
        }
        __syncthreads();
    }
}

// ---------------- host launch ----------------
extern "C" void kernel_launch(void* const* d_in, const int* in_sizes, int n_in,
                              void* d_out, int out_size)
{
    const float* x     = (const float*)d_in[0];
    const int*   ei    = (const int*)d_in[1];
    const int*   batch = (const int*)d_in[2];
    const float* ceW1  = (const float*)d_in[3];
    const float* ceb1  = (const float*)d_in[4];
    const float* ceW2  = (const float*)d_in[5];
    const float* ceb2  = (const float*)d_in[6];
    const float* ceeps = (const float*)d_in[7];
    const float* clW1  = (const float*)d_in[8];
    const float* clb1  = (const float*)d_in[9];
    const float* clW2  = (const float*)d_in[10];
    const float* clb2  = (const float*)d_in[11];
    const float* cleps = (const float*)d_in[12];
    const float* nmW1  = (const float*)d_in[13];
    const float* nmb1  = (const float*)d_in[14];
    const float* nmW2  = (const float*)d_in[15];
    const float* nmb2  = (const float*)d_in[16];
    const float* emW1  = (const float*)d_in[17];
    const float* emb1  = (const float*)d_in[18];
    const float* emW2  = (const float*)d_in[19];
    const float* emb2  = (const float*)d_in[20];
    const float* fmW1  = (const float*)d_in[21];
    const float* fmb1  = (const float*)d_in[22];
    const float* fmW2  = (const float*)d_in[23];
    const float* fmb2  = (const float*)d_in[24];
    const float* clfW  = (const float*)d_in[25];
    const float* clfb  = (const float*)d_in[26];

    const int* src = ei;
    const int* dst = ei + EE;

    float* Z_p;     cudaGetSymbolAddress((void**)&Z_p, g_Z);
    float* h0_p;    cudaGetSymbolAddress((void**)&h0_p, g_h0);
    float* h1_p;    cudaGetSymbolAddress((void**)&h1_p, g_h1);
    float* poolZ_p; cudaGetSymbolAddress((void**)&poolZ_p, g_poolZ);
    float* poolS_p; cudaGetSymbolAddress((void**)&poolS_p, g_poolS);

    float* out        = (float*)d_out;
    float* out_logits = out;
    float* out_hstab  = out_logits + NB_BATCH * KK * CC;
    float* out_horig  = out_hstab + NB_BATCH * KK * HH;
    float* out_nm     = out_horig + NB_BATCH * HH;
    float* out_em     = out_nm + (size_t)NN * KK;
    float* out_fm     = out_em + (size_t)EE * KK;

    const int GB = (NN + 63) / 64;          // 782
    const int GC = NN / 16;                 // 3125
    const int EG = (EE + 255) / 256;        // 3125
    const int EM_GRID = NN / 16;            // 3125
    const int IG = (KK * NB_BATCH * HH + 255) / 256;

    // ---- CSR build + init + weight pre-split ----
    init_kernel<<<IG, 256>>>();
    prep_kernel<<<32, 256>>>(ceW1, ceW2, clW1, clW2, nmW1, emW1, fmW1, fmW2);
    histcnt_kernel<<<EG, 256>>>(dst, batch);
    scan_kernel<<<1, 1024>>>();
    fill_kernel<<<EG, 256>>>(src, dst);

    // ---- causal encoder GIN (3 layers); layer 3 fuses Z pooling ----
    ginenc_kernel<<<GB, 256>>>(x, h1_p, ceeps, 0, 0, 3, ceb1, ceb2, nullptr, nullptr);
    ginenc_kernel<<<GB, 256>>>(h1_p, h0_p, ceeps, 1, 1, 4, ceb1 + 64, ceb2 + 64,
                               nullptr, nullptr);
    ginenc_kernel<<<GB, 256>>>(h0_p, Z_p, ceeps, 2, 2, 5, ceb1 + 128, ceb2 + 128,
                               poolZ_p, batch);

    // ---- masks (writes interleaved g_h0) ----
    mask_kernel<<<dim3(GB, KK), 256>>>(Z_p, x, nmb1, nmW2, nmb2, fmb1, fmb2,
                                       out_nm, out_fm);
    edge_mask_kernel<<<EM_GRID, 256>>>(emb1, emW2, emb2, out_em);

    // ---- classifier GIN (3 layers, all K); layer 3 fuses pooling ----
    gincl_kernel<<<GC, 256>>>(h0_p, h1_p, cleps, 0, 6, 9, clb1, clb2,
                              nullptr, nullptr);
    gincl_kernel<<<GC, 256>>>(h1_p, h0_p, cleps, 1, 7, 10, clb1 + 64, clb2 + 64,
                              nullptr, nullptr);
    gincl_kernel<<<GC, 256>>>(h0_p, h1_p, cleps, 2, 8, 11, clb1 + 128, clb2 + 128,
                              poolS_p, batch);

    // ---- finalize ----
    finalize_kernel<<<NB_BATCH, 64>>>(clfW, clfb, out_logits, out_hstab, out_horig);
}

// round 17
// speedup vs baseline: 1.0406x; 1.0406x over previous
#include <cuda_runtime.h>
#include <math.h>
#include <stdint.h>

#define NN 50000
#define EE 800000
#define HH 64
#define FF 64
#define CC 10
#define KK 4
#define LL 3
#define NB_BATCH 256
#define SPAD 68
#define WSPAD 72
#define SCAN_BLKS 49

// ---------------- device scratch ----------------
__device__ float g_Z[NN * HH];
__device__ float g_h0[(size_t)NN * KK * HH];
__device__ float g_h1[(size_t)NN * KK * HH];
__device__ float g_AB[(size_t)KK * NN * 128];
__device__ float g_ewc[(size_t)EE * KK];
__device__ int   g_deg[NN];
__device__ int   g_off[NN + 1];
__device__ int   g_fill[NN];
__device__ int   g_bsum[SCAN_BLKS];
__device__ int   g_boff[SCAN_BLKS];
__device__ int   g_csr_src[EE + 4];
__device__ int   g_csr_eid[EE];
__device__ float g_poolZ[NB_BATCH * HH];
__device__ float g_poolS[KK * NB_BATCH * HH];
__device__ int   g_cnt[NB_BATCH];

__device__ __forceinline__ void red_add_f2(float* p, float a, float b) {
    asm volatile("red.global.add.v2.f32 [%0], {%1,%2};"
                 :: "l"(p), "f"(a), "f"(b) : "memory");
}
__device__ __forceinline__ float sigmoidf_(float v) { return 1.0f / (1.0f + expf(-v)); }

__device__ __forceinline__ uint32_t tf32_rna(float a) {
    uint32_t h; asm("cvt.rna.tf32.f32 %0, %1;" : "=r"(h) : "f"(a)); return h;
}

__device__ __forceinline__ void loadWsplit(const float* __restrict__ W,
                                           float* Wh, float* Wl, int tid) {
    for (int i = tid; i < 1024; i += 256) {
        float4 w = ((const float4*)W)[i];
        int k = i >> 4, j = (i & 15) * 4;
        float4 h, l;
        h.x = __uint_as_float(tf32_rna(w.x)); l.x = __uint_as_float(tf32_rna(w.x - h.x));
        h.y = __uint_as_float(tf32_rna(w.y)); l.y = __uint_as_float(tf32_rna(w.y - h.y));
        h.z = __uint_as_float(tf32_rna(w.z)); l.z = __uint_as_float(tf32_rna(w.z - h.z));
        h.w = __uint_as_float(tf32_rna(w.w)); l.w = __uint_as_float(tf32_rna(w.w - h.w));
        *((float4*)&Wh[k * WSPAD + j]) = h;
        *((float4*)&Wl[k * WSPAD + j]) = l;
    }
}

#define MMA_TF32(c, A0, A1, A2, A3, B0, B1) \
    asm("mma.sync.aligned.m16n8k8.row.col.f32.tf32.tf32.f32 " \
        "{%0,%1,%2,%3}, {%4,%5,%6,%7}, {%8,%9}, {%0,%1,%2,%3};" \
        : "+f"((c)[0]), "+f"((c)[1]), "+f"((c)[2]), "+f"((c)[3]) \
        : "r"(A0), "r"(A1), "r"(A2), "r"(A3), "r"(B0), "r"(B1))

__device__ __forceinline__ void gemm_frag(const float* As, const float* Wh,
                                          const float* Wl, float c[4][4],
                                          int lane, int warp) {
    int mband = (warp & 3) * 16, nhalf = (warp >> 2) * 32;
    int lr = lane >> 2, lc = lane & 3;
    #pragma unroll
    for (int nt = 0; nt < 4; nt++)
        #pragma unroll
        for (int q = 0; q < 4; q++) c[nt][q] = 0.f;
    #pragma unroll
    for (int ks = 0; ks < 8; ks++) {
        int k0 = ks * 8;
        float a0 = As[(mband + lr) * SPAD + k0 + lc];
        float a1 = As[(mband + 8 + lr) * SPAD + k0 + lc];
        float a2 = As[(mband + lr) * SPAD + k0 + 4 + lc];
        float a3 = As[(mband + 8 + lr) * SPAD + k0 + 4 + lc];
        uint32_t ah0 = tf32_rna(a0), ah1 = tf32_rna(a1);
        uint32_t ah2 = tf32_rna(a2), ah3 = tf32_rna(a3);
        uint32_t al0 = tf32_rna(a0 - __uint_as_float(ah0));
        uint32_t al1 = tf32_rna(a1 - __uint_as_float(ah1));
        uint32_t al2 = tf32_rna(a2 - __uint_as_float(ah2));
        uint32_t al3 = tf32_rna(a3 - __uint_as_float(ah3));
        #pragma unroll
        for (int nt = 0; nt < 4; nt++) {
            int n = nhalf + nt * 8 + lr;
            uint32_t bh0 = __float_as_uint(Wh[(k0 + lc) * WSPAD + n]);
            uint32_t bl0 = __float_as_uint(Wl[(k0 + lc) * WSPAD + n]);
            uint32_t bh1 = __float_as_uint(Wh[(k0 + 4 + lc) * WSPAD + n]);
            uint32_t bl1 = __float_as_uint(Wl[(k0 + 4 + lc) * WSPAD + n]);
            MMA_TF32(c[nt], ah0, ah1, ah2, ah3, bh0, bh1);
            MMA_TF32(c[nt], al0, al1, al2, al3, bh0, bh1);
            MMA_TF32(c[nt], ah0, ah1, ah2, ah3, bl0, bl1);
        }
    }
}

__device__ __forceinline__ void stage_frag(const float c[4][4], float* Cs,
                                           int lane, int warp) {
    int mband = (warp & 3) * 16, nhalf = (warp >> 2) * 32;
    int lr = lane >> 2, lc = lane & 3;
    #pragma unroll
    for (int nt = 0; nt < 4; nt++) {
        int col = nhalf + nt * 8 + lc * 2;
        *((float2*)&Cs[(mband + lr) * SPAD + col])     = make_float2(c[nt][0], c[nt][1]);
        *((float2*)&Cs[(mband + 8 + lr) * SPAD + col]) = make_float2(c[nt][2], c[nt][3]);
    }
}

__device__ __forceinline__ void read_acc(const float* Cs, float acc[4][4],
                                         int tx, int ty) {
    #pragma unroll
    for (int i = 0; i < 4; i++) {
        float4 v = *((const float4*)&Cs[(ty * 4 + i) * SPAD + tx * 4]);
        acc[i][0] = v.x; acc[i][1] = v.y; acc[i][2] = v.z; acc[i][3] = v.w;
    }
}

__device__ __forceinline__ void frag_relu_to_As(const float c[4][4], const float* bsh,
                                                float* As, int lane, int warp) {
    int mband = (warp & 3) * 16, nhalf = (warp >> 2) * 32;
    int lr = lane >> 2, lc = lane & 3;
    #pragma unroll
    for (int nt = 0; nt < 4; nt++) {
        int col = nhalf + nt * 8 + lc * 2;
        float b0 = bsh[col], b1 = bsh[col + 1];
        *((float2*)&As[(mband + lr) * SPAD + col]) =
            make_float2(fmaxf(c[nt][0] + b0, 0.f), fmaxf(c[nt][1] + b1, 0.f));
        *((float2*)&As[(mband + 8 + lr) * SPAD + col]) =
            make_float2(fmaxf(c[nt][2] + b0, 0.f), fmaxf(c[nt][3] + b1, 0.f));
    }
}

// ---------------- init ----------------
__global__ __launch_bounds__(256) void init_kernel() {
    int i = blockIdx.x * 256 + threadIdx.x;
    if (i < NN) { g_deg[i] = 0; g_fill[i] = 0; }
    if (i < NB_BATCH) g_cnt[i] = 0;
    if (i < NB_BATCH * HH) g_poolZ[i] = 0.f;
    if (i < KK * NB_BATCH * HH) g_poolS[i] = 0.f;
    if (i < 4) g_csr_src[EE + i] = 0;
}

__global__ __launch_bounds__(256) void histcnt_kernel(const int* __restrict__ dst,
                                                      const int* __restrict__ batch) {
    int e = blockIdx.x * 256 + threadIdx.x;
    if (e < EE) atomicAdd(&g_deg[dst[e]], 1);
    if (e < NN) atomicAdd(&g_cnt[batch[e]], 1);
}

// ---------------- parallel 3-phase scan ----------------
// A: per-chunk (1024) exclusive scan into g_off; chunk total into g_bsum
__global__ __launch_bounds__(1024) void scanA_kernel() {
    __shared__ int wsum[32];
    int tid = threadIdx.x, lane = tid & 31, wid = tid >> 5;
    int base = blockIdx.x * 1024;
    int v = (base + tid < NN) ? g_deg[base + tid] : 0;
    int inc = v;
    #pragma unroll
    for (int off = 1; off < 32; off <<= 1) {
        int t = __shfl_up_sync(0xffffffffu, inc, off);
        if (lane >= off) inc += t;
    }
    if (lane == 31) wsum[wid] = inc;
    __syncthreads();
    if (wid == 0) {
        int s = wsum[lane];
        #pragma unroll
        for (int off = 1; off < 32; off <<= 1) {
            int t = __shfl_up_sync(0xffffffffu, s, off);
            if (lane >= off) s += t;
        }
        wsum[lane] = s;
    }
    __syncthreads();
    int wpre = wid ? wsum[wid - 1] : 0;
    if (base + tid < NN) g_off[base + tid] = wpre + inc - v;
    if (tid == 1023) g_bsum[blockIdx.x] = wsum[31];
}

// B: scan chunk totals (SCAN_BLKS <= 64)
__global__ __launch_bounds__(64) void scanB_kernel() {
    int tid = threadIdx.x;
    int v = (tid < SCAN_BLKS) ? g_bsum[tid] : 0;
    int inc = v;
    #pragma unroll
    for (int off = 1; off < 32; off <<= 1) {
        int t = __shfl_up_sync(0xffffffffu, inc, off, 32);
        if ((tid & 31) >= off) inc += t;
    }
    __shared__ int w0tot;
    if (tid == 31) w0tot = inc;
    __syncthreads();
    int excl = inc - v + ((tid >= 32) ? w0tot : 0);
    if (tid < SCAN_BLKS) g_boff[tid] = excl;
    if (tid == SCAN_BLKS - 1) g_off[NN] = excl + v;
}

// C: add chunk offsets
__global__ __launch_bounds__(1024) void scanC_kernel() {
    int i = blockIdx.x * 1024 + threadIdx.x;
    if (i < NN && blockIdx.x > 0) g_off[i] += g_boff[blockIdx.x];
}

__global__ __launch_bounds__(256) void fill_kernel(const int* __restrict__ src,
                                                   const int* __restrict__ dst) {
    int e = blockIdx.x * 256 + threadIdx.x;
    if (e < EE) {
        int d = dst[e];
        int pos = g_off[d] + atomicAdd(&g_fill[d], 1);
        g_csr_src[pos] = src[e];
        g_csr_eid[pos] = e;
    }
}

// ---------------- encoder GIN layer ----------------
__global__ __launch_bounds__(256) void ginenc_kernel(
    const float* __restrict__ hin, float* __restrict__ hout,
    const float* __restrict__ eps_ptr, int lidx,
    const float* __restrict__ W1, const float* __restrict__ b1,
    const float* __restrict__ W2, const float* __restrict__ b2,
    float* __restrict__ pool, const int* __restrict__ batch)
{
    __shared__ __align__(16) float As[64 * SPAD];
    __shared__ __align__(16) float Wh[64 * WSPAD];
    __shared__ __align__(16) float Wl[64 * WSPAD];
    __shared__ float bsh[64], bsh2[64];
    int tid = threadIdx.x;
    int r0 = blockIdx.x * 64;
    float epsv = 1.0f + eps_ptr[lidx];
    int part = tid & 15, grp = tid >> 4;
    int lane = tid & 31, warp = tid >> 5;

    #pragma unroll
    for (int rr = 0; rr < 4; rr++) {
        int row = rr * 16 + grp;
        int gr = r0 + row;
        float4 a = make_float4(0.f, 0.f, 0.f, 0.f);
        if (gr < NN) {
            float4 h = ((const float4*)(hin + (size_t)gr * HH))[part];
            a.x = epsv * h.x; a.y = epsv * h.y; a.z = epsv * h.z; a.w = epsv * h.w;
            int beg = g_off[gr], end = g_off[gr + 1];
            int p = beg;
            int sA = g_csr_src[p], sB = g_csr_src[p + 1];
            for (; p + 1 < end; p += 2) {
                int s0 = sA, s1 = sB;
                sA = g_csr_src[p + 2]; sB = g_csr_src[p + 3];
                float4 v0 = ((const float4*)(hin + (size_t)s0 * HH))[part];
                float4 v1 = ((const float4*)(hin + (size_t)s1 * HH))[part];
                a.x += v0.x + v1.x; a.y += v0.y + v1.y;
                a.z += v0.z + v1.z; a.w += v0.w + v1.w;
            }
            if (p < end) {
                float4 v0 = ((const float4*)(hin + (size_t)sA * HH))[part];
                a.x += v0.x; a.y += v0.y; a.z += v0.z; a.w += v0.w;
            }
        }
        *((float4*)&As[row * SPAD + part * 4]) = a;
    }

    loadWsplit(W1, Wh, Wl, tid);
    if (tid < 64) { bsh[tid] = b1[tid]; bsh2[tid] = b2[tid]; }
    __syncthreads();

    float c[4][4];
    gemm_frag(As, Wh, Wl, c, lane, warp);
    __syncthreads();
    frag_relu_to_As(c, bsh, As, lane, warp);
    loadWsplit(W2, Wh, Wl, tid);
    __syncthreads();
    gemm_frag(As, Wh, Wl, c, lane, warp);

    {
        int mband = (warp & 3) * 16, nhalf = (warp >> 2) * 32;
        int lr = lane >> 2, lc = lane & 3;
        int ga = r0 + mband + lr, gb = r0 + mband + 8 + lr;
        int bA = 0, bB = 0;
        if (pool) {
            if (ga < NN) bA = batch[ga];
            if (gb < NN) bB = batch[gb];
        }
        #pragma unroll
        for (int nt = 0; nt < 4; nt++) {
            int col = nhalf + nt * 8 + lc * 2;
            float b0 = bsh2[col], b1v = bsh2[col + 1];
            if (ga < NN) {
                float ox = fmaxf(c[nt][0] + b0, 0.f), oy = fmaxf(c[nt][1] + b1v, 0.f);
                *((float2*)(hout + (size_t)ga * HH + col)) = make_float2(ox, oy);
                if (pool) red_add_f2(pool + (size_t)bA * HH + col, ox, oy);
            }
            if (gb < NN) {
                float ox = fmaxf(c[nt][2] + b0, 0.f), oy = fmaxf(c[nt][3] + b1v, 0.f);
                *((float2*)(hout + (size_t)gb * HH + col)) = make_float2(ox, oy);
                if (pool) red_add_f2(pool + (size_t)bB * HH + col, ox, oy);
            }
        }
    }
}

// ---------------- classifier GIN layer ----------------
__global__ __launch_bounds__(256) void gincl_kernel(
    const float* __restrict__ hin, float* __restrict__ hout,
    const float* __restrict__ eps_ptr, int lidx,
    const float* __restrict__ W1, const float* __restrict__ b1,
    const float* __restrict__ W2, const float* __restrict__ b2,
    float* __restrict__ pool, const int* __restrict__ batch)
{
    __shared__ __align__(16) float As[64 * SPAD];
    __shared__ __align__(16) float Wh[64 * WSPAD];
    __shared__ __align__(16) float Wl[64 * WSPAD];
    __shared__ float bsh[64], bsh2[64];
    int tid = threadIdx.x;
    int n0 = blockIdx.x * 16;
    float epsv = 1.0f + eps_ptr[lidx];
    int part = tid & 15, grp = tid >> 4;
    int lane = tid & 31, warp = tid >> 5;

    {
        int gr = n0 + grp;
        const float4* hbase = (const float4*)(hin + (size_t)gr * KK * HH);
        float4 a[4];
        #pragma unroll
        for (int k = 0; k < 4; k++) {
            float4 h = hbase[k * 16 + part];
            a[k].x = epsv * h.x; a[k].y = epsv * h.y;
            a[k].z = epsv * h.z; a[k].w = epsv * h.w;
        }
        int beg = g_off[gr], end = g_off[gr + 1];
        int p = beg;
        int sA = g_csr_src[p], sB = g_csr_src[p + 1];
        for (; p + 1 < end; p += 2) {
            int s0 = sA, s1 = sB;
            sA = g_csr_src[p + 2]; sB = g_csr_src[p + 3];
            float4 w0 = *((const float4*)(g_ewc + (size_t)p * 4));
            float4 w1 = *((const float4*)(g_ewc + (size_t)(p + 1) * 4));
            const float4* vb0 = (const float4*)(hin + (size_t)s0 * KK * HH);
            const float4* vb1 = (const float4*)(hin + (size_t)s1 * KK * HH);
            float4 v0 = vb0[0 * 16 + part];
            float4 v1 = vb0[1 * 16 + part];
            float4 v2 = vb0[2 * 16 + part];
            float4 v3 = vb0[3 * 16 + part];
            float4 u0 = vb1[0 * 16 + part];
            float4 u1 = vb1[1 * 16 + part];
            float4 u2 = vb1[2 * 16 + part];
            float4 u3 = vb1[3 * 16 + part];
            a[0].x = fmaf(w0.x, v0.x, a[0].x); a[0].y = fmaf(w0.x, v0.y, a[0].y);
            a[0].z = fmaf(w0.x, v0.z, a[0].z); a[0].w = fmaf(w0.x, v0.w, a[0].w);
            a[1].x = fmaf(w0.y, v1.x, a[1].x); a[1].y = fmaf(w0.y, v1.y, a[1].y);
            a[1].z = fmaf(w0.y, v1.z, a[1].z); a[1].w = fmaf(w0.y, v1.w, a[1].w);
            a[2].x = fmaf(w0.z, v2.x, a[2].x); a[2].y = fmaf(w0.z, v2.y, a[2].y);
            a[2].z = fmaf(w0.z, v2.z, a[2].z); a[2].w = fmaf(w0.z, v2.w, a[2].w);
            a[3].x = fmaf(w0.w, v3.x, a[3].x); a[3].y = fmaf(w0.w, v3.y, a[3].y);
            a[3].z = fmaf(w0.w, v3.z, a[3].z); a[3].w = fmaf(w0.w, v3.w, a[3].w);
            a[0].x = fmaf(w1.x, u0.x, a[0].x); a[0].y = fmaf(w1.x, u0.y, a[0].y);
            a[0].z = fmaf(w1.x, u0.z, a[0].z); a[0].w = fmaf(w1.x, u0.w, a[0].w);
            a[1].x = fmaf(w1.y, u1.x, a[1].x); a[1].y = fmaf(w1.y, u1.y, a[1].y);
            a[1].z = fmaf(w1.y, u1.z, a[1].z); a[1].w = fmaf(w1.y, u1.w, a[1].w);
            a[2].x = fmaf(w1.z, u2.x, a[2].x); a[2].y = fmaf(w1.z, u2.y, a[2].y);
            a[2].z = fmaf(w1.z, u2.z, a[2].z); a[2].w = fmaf(w1.z, u2.w, a[2].w);
            a[3].x = fmaf(w1.w, u3.x, a[3].x); a[3].y = fmaf(w1.w, u3.y, a[3].y);
            a[3].z = fmaf(w1.w, u3.z, a[3].z); a[3].w = fmaf(w1.w, u3.w, a[3].w);
        }
        if (p < end) {
            float4 w0 = *((const float4*)(g_ewc + (size_t)p * 4));
            const float4* vb = (const float4*)(hin + (size_t)sA * KK * HH);
            float4 v0 = vb[0 * 16 + part];
            float4 v1 = vb[1 * 16 + part];
            float4 v2 = vb[2 * 16 + part];
            float4 v3 = vb[3 * 16 + part];
            a[0].x = fmaf(w0.x, v0.x, a[0].x); a[0].y = fmaf(w0.x, v0.y, a[0].y);
            a[0].z = fmaf(w0.x, v0.z, a[0].z); a[0].w = fmaf(w0.x, v0.w, a[0].w);
            a[1].x = fmaf(w0.y, v1.x, a[1].x); a[1].y = fmaf(w0.y, v1.y, a[1].y);
            a[1].z = fmaf(w0.y, v1.z, a[1].z); a[1].w = fmaf(w0.y, v1.w, a[1].w);
            a[2].x = fmaf(w0.z, v2.x, a[2].x); a[2].y = fmaf(w0.z, v2.y, a[2].y);
            a[2].z = fmaf(w0.z, v2.z, a[2].z); a[2].w = fmaf(w0.z, v2.w, a[2].w);
            a[3].x = fmaf(w0.w, v3.x, a[3].x); a[3].y = fmaf(w0.w, v3.y, a[3].y);
            a[3].z = fmaf(w0.w, v3.z, a[3].z); a[3].w = fmaf(w0.w, v3.w, a[3].w);
        }
        #pragma unroll
        for (int k = 0; k < 4; k++)
            *((float4*)&As[(grp * 4 + k) * SPAD + part * 4]) = a[k];
    }

    loadWsplit(W1, Wh, Wl, tid);
    if (tid < 64) { bsh[tid] = b1[tid]; bsh2[tid] = b2[tid]; }
    __syncthreads();

    float c[4][4];
    gemm_frag(As, Wh, Wl, c, lane, warp);
    __syncthreads();
    frag_relu_to_As(c, bsh, As, lane, warp);
    loadWsplit(W2, Wh, Wl, tid);
    __syncthreads();
    gemm_frag(As, Wh, Wl, c, lane, warp);

    {
        int mband = (warp & 3) * 16, nhalf = (warp >> 2) * 32;
        int lr = lane >> 2, lc = lane & 3;
        int ra = mband + lr, rb = mband + 8 + lr;
        int gna = n0 + (ra >> 2), kea = ra & 3;
        int gnb = n0 + (rb >> 2), keb = rb & 3;
        int bA = 0, bB = 0;
        if (pool) { bA = batch[gna]; bB = batch[gnb]; }
        float* ha = hout + ((size_t)gna * KK + kea) * HH;
        float* hb = hout + ((size_t)gnb * KK + keb) * HH;
        #pragma unroll
        for (int nt = 0; nt < 4; nt++) {
            int col = nhalf + nt * 8 + lc * 2;
            float b0 = bsh2[col], b1v = bsh2[col + 1];
            float ox = fmaxf(c[nt][0] + b0, 0.f), oy = fmaxf(c[nt][1] + b1v, 0.f);
            *((float2*)(ha + col)) = make_float2(ox, oy);
            if (pool) red_add_f2(pool + ((size_t)kea * NB_BATCH + bA) * HH + col, ox, oy);
            float px = fmaxf(c[nt][2] + b0, 0.f), py = fmaxf(c[nt][3] + b1v, 0.f);
            *((float2*)(hb + col)) = make_float2(px, py);
            if (pool) red_add_f2(pool + ((size_t)keb * NB_BATCH + bB) * HH + col, px, py);
        }
    }
}

// ---------------- fused mask kernel ----------------
__global__ __launch_bounds__(256) void mask_kernel(
    const float* __restrict__ Z, const float* __restrict__ x,
    const float* __restrict__ nmW1, const float* __restrict__ nmb1,
    const float* __restrict__ nmW2, const float* __restrict__ nmb2,
    const float* __restrict__ emW1,
    const float* __restrict__ fmW1, const float* __restrict__ fmb1,
    const float* __restrict__ fmW2, const float* __restrict__ fmb2,
    float* __restrict__ out_nm, float* __restrict__ out_fm)
{
    __shared__ __align__(16) float As[64 * SPAD];
    __shared__ __align__(16) float Wh[64 * WSPAD];
    __shared__ __align__(16) float Wl[64 * WSPAD];
    __shared__ float bsh[64], bsh2[64], w2s[64], nmv[64];
    int tid = threadIdx.x, r0 = blockIdx.x * 64;
    int k = blockIdx.y;
    int lane = tid & 31, warp = tid >> 5;
    int mband = (warp & 3) * 16, nhalf = (warp >> 2) * 32;
    int lr = lane >> 2, lc = lane & 3;
    const float* nmW1k = nmW1 + (size_t)k * 4096;
    const float* nmb1k = nmb1 + (size_t)k * 64;
    const float* nmW2k = nmW2 + (size_t)k * 64;
    const float* emW1k = emW1 + (size_t)k * 8192;
    const float* fmW1k = fmW1 + (size_t)k * 4096;
    const float* fmb1k = fmb1 + (size_t)k * 64;
    const float* fmW2k = fmW2 + (size_t)k * 4096;
    const float* fmb2k = fmb2 + (size_t)k * 64;
    float* ABk = g_AB + (size_t)k * NN * 128;

    {
        int row = tid >> 2, p0 = (tid & 3) * 4, gr = r0 + row;
        #pragma unroll
        for (int q = 0; q < 4; q++) {
            float4 v = make_float4(0.f, 0.f, 0.f, 0.f);
            if (gr < NN) v = ((const float4*)(Z + (size_t)gr * HH))[p0 + q];
            *((float4*)&As[row * SPAD + (p0 + q) * 4]) = v;
        }
    }
    int tx = tid & 15, ty = tid >> 4;
    float c[4][4], acc[4][4];
    int ga = r0 + mband + lr, gb = r0 + mband + 8 + lr;

    // ---- node mask (staged, cross-warp reduce) ----
    loadWsplit(nmW1k, Wh, Wl, tid);
    if (tid < 64) { bsh[tid] = nmb1k[tid]; w2s[tid] = nmW2k[tid]; }
    __syncthreads();
    gemm_frag(As, Wh, Wl, c, lane, warp);
    __syncthreads();
    stage_frag(c, Wh, lane, warp);
    __syncthreads();
    read_acc(Wh, acc, tx, ty);
    float b2v = nmb2[k];
    #pragma unroll
    for (int i = 0; i < 4; i++) {
        float p = 0.f;
        #pragma unroll
        for (int j = 0; j < 4; j++)
            p += fmaxf(acc[i][j] + bsh[tx*4+j], 0.f) * w2s[tx*4+j];
        #pragma unroll
        for (int off = 8; off > 0; off >>= 1)
            p += __shfl_down_sync(0xffffffffu, p, off, 16);
        if (tx == 0) {
            float sg = sigmoidf_(p + b2v);
            nmv[ty * 4 + i] = sg;
            int gr = r0 + ty * 4 + i;
            if (gr < NN) out_nm[(size_t)gr * KK + k] = sg;
        }
    }
    __syncthreads();

    // ---- AB precompute (fragment-direct) ----
    #pragma unroll
    for (int half = 0; half < 2; half++) {
        loadWsplit(emW1k + half * 4096, Wh, Wl, tid);
        __syncthreads();
        gemm_frag(As, Wh, Wl, c, lane, warp);
        #pragma unroll
        for (int nt = 0; nt < 4; nt++) {
            int col = half * 64 + nhalf + nt * 8 + lc * 2;
            if (ga < NN)
                *((float2*)(ABk + (size_t)ga * 128 + col)) = make_float2(c[nt][0], c[nt][1]);
            if (gb < NN)
                *((float2*)(ABk + (size_t)gb * 128 + col)) = make_float2(c[nt][2], c[nt][3]);
        }
        __syncthreads();
    }

    // ---- feature mask + masked_x ----
    loadWsplit(fmW1k, Wh, Wl, tid);
    if (tid < 64) { bsh[tid] = fmb1k[tid]; bsh2[tid] = fmb2k[tid]; }
    __syncthreads();
    gemm_frag(As, Wh, Wl, c, lane, warp);
    __syncthreads();
    frag_relu_to_As(c, bsh, As, lane, warp);
    loadWsplit(fmW2k, Wh, Wl, tid);
    __syncthreads();
    gemm_frag(As, Wh, Wl, c, lane, warp);

    {
        float nmu_a = (ga < NN) ? nmv[mband + lr] : 0.f;
        float nmu_b = (gb < NN) ? nmv[mband + 8 + lr] : 0.f;
        #pragma unroll
        for (int nt = 0; nt < 4; nt++) {
            int col = nhalf + nt * 8 + lc * 2;
            float b0 = bsh2[col], b1v = bsh2[col + 1];
            if (ga < NN) {
                float2 xr = *((const float2*)(x + (size_t)ga * FF + col));
                float sx = sigmoidf_(c[nt][0] + b0), sy = sigmoidf_(c[nt][1] + b1v);
                *((float2*)(out_fm + ((size_t)ga * KK + k) * FF + col)) = make_float2(sx, sy);
                *((float2*)(g_h0 + ((size_t)ga * KK + k) * HH + col)) =
                    make_float2(xr.x * nmu_a * sx, xr.y * nmu_a * sy);
            }
            if (gb < NN) {
                float2 xr = *((const float2*)(x + (size_t)gb * FF + col));
                float sx = sigmoidf_(c[nt][2] + b0), sy = sigmoidf_(c[nt][3] + b1v);
                *((float2*)(out_fm + ((size_t)gb * KK + k) * FF + col)) = make_float2(sx, sy);
                *((float2*)(g_h0 + ((size_t)gb * KK + k) * HH + col)) =
                    make_float2(xr.x * nmu_b * sx, xr.y * nmu_b * sy);
            }
        }
    }
}

// ---------------- edge mask: CSR-row-tiled, ALL K experts in one pass ----------------
__global__ __launch_bounds__(256) void edge_mask_kernel(
    const float* __restrict__ emb1, const float* __restrict__ emW2,
    const float* __restrict__ emb2, float* __restrict__ out_em)
{
    __shared__ __align__(16) float b1s[4][64];
    __shared__ __align__(16) float w2s[4][64];
    int tid = threadIdx.x;
    {
        int kk = tid >> 6, j = tid & 63;
        b1s[kk][j] = emb1[kk * 64 + j];
        w2s[kk][j] = emW2[kk * 64 + j];
    }
    __syncthreads();
    int lane = tid & 15, grp = tid >> 4;
    int gr = blockIdx.x * 16 + grp;

    float4 bb[4], w[4];
    float b2v[4];
    #pragma unroll
    for (int k = 0; k < 4; k++) {
        const float* ABk = g_AB + (size_t)k * NN * 128;
        float4 b = *((const float4*)(ABk + (size_t)gr * 128 + 64) + lane);
        float4 bi = ((const float4*)b1s[k])[lane];
        bb[k] = make_float4(b.x + bi.x, b.y + bi.y, b.z + bi.z, b.w + bi.w);
        w[k] = ((const float4*)w2s[k])[lane];
        b2v[k] = emb2[k];
    }

    int beg = g_off[gr], end = g_off[gr + 1];
    for (int p = beg; p < end; p++) {
        int s = g_csr_src[p];
        float pp[4];
        #pragma unroll
        for (int k = 0; k < 4; k++) {
            const float* ABk = g_AB + (size_t)k * NN * 128;
            float4 a = *((const float4*)(ABk + (size_t)s * 128) + lane);
            pp[k] = fmaxf(a.x + bb[k].x, 0.f) * w[k].x
                  + fmaxf(a.y + bb[k].y, 0.f) * w[k].y
                  + fmaxf(a.z + bb[k].z, 0.f) * w[k].z
                  + fmaxf(a.w + bb[k].w, 0.f) * w[k].w;
        }
        #pragma unroll
        for (int off = 8; off > 0; off >>= 1) {
            pp[0] += __shfl_down_sync(0xffffffffu, pp[0], off, 16);
            pp[1] += __shfl_down_sync(0xffffffffu, pp[1], off, 16);
            pp[2] += __shfl_down_sync(0xffffffffu, pp[2], off, 16);
            pp[3] += __shfl_down_sync(0xffffffffu, pp[3], off, 16);
        }
        if (lane == 0) {
            float4 sg;
            sg.x = sigmoidf_(pp[0] + b2v[0]);
            sg.y = sigmoidf_(pp[1] + b2v[1]);
            sg.z = sigmoidf_(pp[2] + b2v[2]);
            sg.w = sigmoidf_(pp[3] + b2v[3]);
            *((float4*)(g_ewc + (size_t)p * 4)) = sg;
            *((float4*)(out_em + (size_t)g_csr_eid[p] * 4)) = sg;
        }
    }
}

// ---------------- finalize ----------------
__global__ __launch_bounds__(64) void finalize_kernel(
    const float* __restrict__ clfW, const float* __restrict__ clfb,
    float* __restrict__ out_logits, float* __restrict__ out_hstab,
    float* __restrict__ out_horig)
{
    int b = blockIdx.x, t = threadIdx.x;
    __shared__ float hs[64];
    float inv = 1.0f / fmaxf((float)g_cnt[b], 1.0f);
    out_horig[b * HH + t] = g_poolZ[b * HH + t] * inv;
    for (int k = 0; k < KK; k++) {
        float v = g_poolS[((size_t)k * NB_BATCH + b) * HH + t] * inv;
        out_hstab[((size_t)b * KK + k) * HH + t] = v;
        hs[t] = v;
        __syncthreads();
        if (t < CC) {
            float sacc = clfb[k * CC + t];
            #pragma unroll 8
            for (int h2 = 0; h2 < HH; h2++)
                sacc += hs[h2] * clfW[((size_t)k * HH + h2) * CC + t];
            out_logits[((size_t)b * KK + k) * CC + t] = sacc;
        }
        __syncthreads();
    }
}

// ---------------- host launch ----------------
extern "C" void kernel_launch(void* const* d_in, const int* in_sizes, int n_in,
                              void* d_out, int out_size)
{
    const float* x     = (const float*)d_in[0];
    const int*   ei    = (const int*)d_in[1];
    const int*   batch = (const int*)d_in[2];
    const float* ceW1  = (const float*)d_in[3];
    const float* ceb1  = (const float*)d_in[4];
    const float* ceW2  = (const float*)d_in[5];
    const float* ceb2  = (const float*)d_in[6];
    const float* ceeps = (const float*)d_in[7];
    const float* clW1  = (const float*)d_in[8];
    const float* clb1  = (const float*)d_in[9];
    const float* clW2  = (const float*)d_in[10];
    const float* clb2  = (const float*)d_in[11];
    const float* cleps = (const float*)d_in[12];
    const float* nmW1  = (const float*)d_in[13];
    const float* nmb1  = (const float*)d_in[14];
    const float* nmW2  = (const float*)d_in[15];
    const float* nmb2  = (const float*)d_in[16];
    const float* emW1  = (const float*)d_in[17];
    const float* emb1  = (const float*)d_in[18];
    const float* emW2  = (const float*)d_in[19];
    const float* emb2  = (const float*)d_in[20];
    const float* fmW1  = (const float*)d_in[21];
    const float* fmb1  = (const float*)d_in[22];
    const float* fmW2  = (const float*)d_in[23];
    const float* fmb2  = (const float*)d_in[24];
    const float* clfW  = (const float*)d_in[25];
    const float* clfb  = (const float*)d_in[26];

    const int* src = ei;
    const int* dst = ei + EE;

    float* Z_p;     cudaGetSymbolAddress((void**)&Z_p, g_Z);
    float* h0_p;    cudaGetSymbolAddress((void**)&h0_p, g_h0);
    float* h1_p;    cudaGetSymbolAddress((void**)&h1_p, g_h1);
    float* poolZ_p; cudaGetSymbolAddress((void**)&poolZ_p, g_poolZ);
    float* poolS_p; cudaGetSymbolAddress((void**)&poolS_p, g_poolS);

    float* out        = (float*)d_out;
    float* out_logits = out;
    float* out_hstab  = out_logits + NB_BATCH * KK * CC;
    float* out_horig  = out_hstab + NB_BATCH * KK * HH;
    float* out_nm     = out_horig + NB_BATCH * HH;
    float* out_em     = out_nm + (size_t)NN * KK;
    float* out_fm     = out_em + (size_t)EE * KK;

    const int GB = (NN + 63) / 64;          // 782
    const int GC = NN / 16;                 // 3125
    const int EG = (EE + 255) / 256;        // 3125
    const int EM_GRID = NN / 16;            // 3125
    const int IG = (KK * NB_BATCH * HH + 255) / 256;

    // ---- CSR build + init (parallel scan) ----
    init_kernel<<<IG, 256>>>();
    histcnt_kernel<<<EG, 256>>>(dst, batch);
    scanA_kernel<<<SCAN_BLKS, 1024>>>();
    scanB_kernel<<<1, 64>>>();
    scanC_kernel<<<SCAN_BLKS, 1024>>>();
    fill_kernel<<<EG, 256>>>(src, dst);

    // ---- causal encoder GIN (3 layers); layer 3 fuses Z pooling ----
    ginenc_kernel<<<GB, 256>>>(x, h1_p, ceeps, 0, ceW1, ceb1, ceW2, ceb2, nullptr, nullptr);
    ginenc_kernel<<<GB, 256>>>(h1_p, h0_p, ceeps, 1, ceW1 + 4096, ceb1 + 64,
                               ceW2 + 4096, ceb2 + 64, nullptr, nullptr);
    ginenc_kernel<<<GB, 256>>>(h0_p, Z_p, ceeps, 2, ceW1 + 8192, ceb1 + 128,
                               ceW2 + 8192, ceb2 + 128, poolZ_p, batch);

    // ---- masks (writes interleaved g_h0) ----
    mask_kernel<<<dim3(GB, KK), 256>>>(Z_p, x, nmW1, nmb1, nmW2, nmb2,
                                       emW1, fmW1, fmb1, fmW2, fmb2,
                                       out_nm, out_fm);
    edge_mask_kernel<<<EM_GRID, 256>>>(emb1, emW2, emb2, out_em);

    // ---- classifier GIN (3 layers, all K); layer 3 fuses pooling ----
    gincl_kernel<<<GC, 256>>>(h0_p, h1_p, cleps, 0, clW1, clb1, clW2, clb2,
                              nullptr, nullptr);
    gincl_kernel<<<GC, 256>>>(h1_p, h0_p, cleps, 1, clW1 + 4096, clb1 + 64,
                              clW2 + 4096, clb2 + 64, nullptr, nullptr);
    gincl_kernel<<<GC, 256>>>(h0_p, h1_p, cleps, 2, clW1 + 8192, clb1 + 128,
                              clW2 + 8192, clb2 + 128, poolS_p, batch);

    // ---- finalize ----
    finalize_kernel<<<NB_BATCH, 64>>>(clfW, clfb, out_logits, out_hstab, out_horig);
}